// round 2
// baseline (speedup 1.0000x reference)
#include <cuda_runtime.h>
#include <cuda_bf16.h>
#include <cstdint>
#include <math.h>

#define NTOK 8192
#define CDIM 1024
#define HDIM 2048
#define NEXP 8

#define BM 128
#define BN 128
#define BK 32
#define APAD 8
#define BPAD 8

// ---------------- device scratch (no allocations allowed) ----------------
__device__ __nv_bfloat16 g_xb[NTOK * CDIM];   // x in bf16
__device__ __nv_bfloat16 g_h[NTOK * HDIM];    // hidden activations bf16
__device__ int   g_tok[NEXP * NTOK];          // token ids per expert bucket
__device__ int   g_cnt[NEXP];                 // bucket counts
__device__ float g_score[NTOK];               // top-1 gate value per token
__device__ float g_xsum[NTOK];                // exact fp32 sum_k x[t,k]

// ---------------- small helpers ----------------
__device__ __forceinline__ uint32_t smem_u32(const void* p) {
    return static_cast<uint32_t>(__cvta_generic_to_shared(p));
}
__device__ __forceinline__ void ldsm_x4(uint32_t r[4], uint32_t addr) {
    asm volatile("ldmatrix.sync.aligned.m8n8.x4.shared.b16 {%0,%1,%2,%3}, [%4];"
                 : "=r"(r[0]), "=r"(r[1]), "=r"(r[2]), "=r"(r[3]) : "r"(addr));
}
__device__ __forceinline__ void ldsm_x4t(uint32_t r[4], uint32_t addr) {
    asm volatile("ldmatrix.sync.aligned.m8n8.x4.trans.shared.b16 {%0,%1,%2,%3}, [%4];"
                 : "=r"(r[0]), "=r"(r[1]), "=r"(r[2]), "=r"(r[3]) : "r"(addr));
}
__device__ __forceinline__ void mma_bf16(float c[4], const uint32_t a[4],
                                         uint32_t b0, uint32_t b1) {
    asm volatile(
        "mma.sync.aligned.m16n8k16.row.col.f32.bf16.bf16.f32 "
        "{%0,%1,%2,%3}, {%4,%5,%6,%7}, {%8,%9}, {%0,%1,%2,%3};\n"
        : "+f"(c[0]), "+f"(c[1]), "+f"(c[2]), "+f"(c[3])
        : "r"(a[0]), "r"(a[1]), "r"(a[2]), "r"(a[3]), "r"(b0), "r"(b1));
}
__device__ __forceinline__ float gelu_exact(float v) {
    return 0.5f * v * (1.0f + erff(v * 0.70710678118654752f));
}

// ---------------- kernel 0: zero bucket counters ----------------
__global__ void zero_cnt_kernel() {
    if (threadIdx.x < NEXP) g_cnt[threadIdx.x] = 0;
}

// ---------------- kernel 1: gating / routing + x->bf16 + exact row sums --
__global__ __launch_bounds__(256) void route_kernel(
    const float* __restrict__ x, const float* __restrict__ Wr,
    const float* __restrict__ wg)
{
    __shared__ float wgn_s[NEXP][16];
    const int tid = threadIdx.x;
    if (tid < NEXP) {
        float row[16];
        float nrm = 0.f;
        #pragma unroll
        for (int j = 0; j < 16; ++j) { row[j] = wg[tid * 16 + j]; nrm += row[j] * row[j]; }
        nrm = fmaxf(sqrtf(nrm), 1e-4f);
        #pragma unroll
        for (int j = 0; j < 16; ++j) wgn_s[tid][j] = row[j] / nrm;
    }
    __syncthreads();

    const int lane = tid & 31;
    const int gw   = (blockIdx.x * blockDim.x + tid) >> 5;  // global warp id
    const int t0   = gw * 4;                                // first of 4 tokens

    float acc[4][16];
    float sx[4] = {0.f, 0.f, 0.f, 0.f};
    #pragma unroll
    for (int ti = 0; ti < 4; ++ti)
        #pragma unroll
        for (int j = 0; j < 16; ++j) acc[ti][j] = 0.f;

    for (int c = 0; c < 32; ++c) {
        const int k = c * 32 + lane;
        float wr[16];
        #pragma unroll
        for (int j = 0; j < 16; ++j) wr[j] = Wr[j * CDIM + k];
        #pragma unroll
        for (int ti = 0; ti < 4; ++ti) {
            float xv = x[(size_t)(t0 + ti) * CDIM + k];
            g_xb[(size_t)(t0 + ti) * CDIM + k] = __float2bfloat16(xv);
            sx[ti] += xv;
            #pragma unroll
            for (int j = 0; j < 16; ++j) acc[ti][j] = fmaf(xv, wr[j], acc[ti][j]);
        }
    }
    // butterfly reduce over lanes -> every lane has full results for 4 tokens
    #pragma unroll
    for (int ti = 0; ti < 4; ++ti) {
        #pragma unroll
        for (int j = 0; j < 16; ++j)
            #pragma unroll
            for (int off = 16; off > 0; off >>= 1)
                acc[ti][j] += __shfl_xor_sync(0xffffffffu, acc[ti][j], off);
        #pragma unroll
        for (int off = 16; off > 0; off >>= 1)
            sx[ti] += __shfl_xor_sync(0xffffffffu, sx[ti], off);
    }

    if (lane < 4) {
        const int t = t0 + lane;
        float logit[NEXP];
        float best = -1e30f; int be = 0;
        #pragma unroll
        for (int e = 0; e < NEXP; ++e) {
            float l = 0.f;
            #pragma unroll
            for (int j = 0; j < 16; ++j) l += acc[lane][j] * wgn_s[e][j];
            logit[e] = l;
            if (l > best) { best = l; be = e; }   // first-max tie rule (argmax)
        }
        float denom = 0.f;
        #pragma unroll
        for (int e = 0; e < NEXP; ++e) denom += expf(logit[e] - best);
        g_score[t] = 1.0f / denom;                // softmax value at argmax
        g_xsum[t]  = sx[lane];                    // exact fp32 row sum of x
        int pos = atomicAdd(&g_cnt[be], 1);
        g_tok[be * NTOK + pos] = t;
    }
}

// ---------------- kernel 2/3: grouped GEMM (bf16 mma.sync, fp32 acc) -----
// FFN1: h = gelu(Ag(x_bf16) @ bf16(W1[e]-0.5) + 0.5*xsum + b1[e]) -> g_h
//   (the rank-1 0.5*sum_k(x) term is carried in exact fp32: this kills the
//    coherent bf16(x) quantization error that W1's positive mean amplifies)
// FFN2: out[token] = (Ag(g_h) @ W2[e] + b2[e]) * score[token]
template<int KDIM, int NDIM, bool FFN1>
__global__ __launch_bounds__(256) void moe_gemm(
    const float* __restrict__ W, const float* __restrict__ bias,
    float* __restrict__ out)
{
    const int e   = blockIdx.z;
    const int cnt = g_cnt[e];
    const int m0  = blockIdx.y * BM;
    if (m0 >= cnt) return;
    const int n0  = blockIdx.x * BN;

    __shared__ __align__(16) __nv_bfloat16 As[2][BM][BK + APAD];
    __shared__ __align__(16) __nv_bfloat16 Bs[2][BK][BN + BPAD];
    __shared__ int toks[BM];

    const int tid  = threadIdx.x;
    const int lane = tid & 31;
    const int wid  = tid >> 5;
    const int wm   = (wid & 3) * 32;   // warp row offset in tile
    const int wn   = (wid >> 2) * 64;  // warp col offset in tile

    const __nv_bfloat16* __restrict__ A = FFN1 ? g_xb : g_h;
    const int lda = FFN1 ? CDIM : HDIM;
    const float* __restrict__ Wb = W + (size_t)e * KDIM * NDIM + n0;
    const float bshift = FFN1 ? 0.5f : 0.0f;

    if (tid < BM) {
        int idx = m0 + tid;
        toks[tid] = g_tok[e * NTOK + min(idx, cnt - 1)];
    }
    __syncthreads();

    // A staging: thread -> (row, 16-half segment)
    const int arow = tid >> 1;
    const int aseg = (tid & 1) * 16;
    const int mytok = toks[arow];
    // B staging: thread -> (k-row, 16-float segment), fp32->bf16 convert
    const int brow = tid >> 3;
    const int bcs  = (tid & 7) * 16;

    uint4  aR[2];
    float4 bR[4];

    auto ldg_tile = [&](int kt) {
        const int k0 = kt * BK;
        const __nv_bfloat16* ap = A + (size_t)mytok * lda + k0 + aseg;
        aR[0] = *reinterpret_cast<const uint4*>(ap);
        aR[1] = *reinterpret_cast<const uint4*>(ap + 8);
        const float* bp = Wb + (size_t)(k0 + brow) * NDIM + bcs;
        bR[0] = reinterpret_cast<const float4*>(bp)[0];
        bR[1] = reinterpret_cast<const float4*>(bp)[1];
        bR[2] = reinterpret_cast<const float4*>(bp)[2];
        bR[3] = reinterpret_cast<const float4*>(bp)[3];
    };
    auto sts_tile = [&](int s) {
        *reinterpret_cast<uint4*>(&As[s][arow][aseg])     = aR[0];
        *reinterpret_cast<uint4*>(&As[s][arow][aseg + 8]) = aR[1];
        uint4 bw[2];
        __nv_bfloat162* bv = reinterpret_cast<__nv_bfloat162*>(bw);
        #pragma unroll
        for (int q = 0; q < 4; ++q) {
            bv[2 * q + 0] = __floats2bfloat162_rn(bR[q].x - bshift, bR[q].y - bshift);
            bv[2 * q + 1] = __floats2bfloat162_rn(bR[q].z - bshift, bR[q].w - bshift);
        }
        *reinterpret_cast<uint4*>(&Bs[s][brow][bcs])     = bw[0];
        *reinterpret_cast<uint4*>(&Bs[s][brow][bcs + 8]) = bw[1];
    };

    float c[2][8][4];
    #pragma unroll
    for (int mi = 0; mi < 2; ++mi)
        #pragma unroll
        for (int ni = 0; ni < 8; ++ni)
            #pragma unroll
            for (int q = 0; q < 4; ++q) c[mi][ni][q] = 0.f;

    const int nk = KDIM / BK;
    ldg_tile(0);
    sts_tile(0);
    __syncthreads();

    for (int kt = 0; kt < nk; ++kt) {
        const int cur = kt & 1;
        if (kt + 1 < nk) ldg_tile(kt + 1);

        #pragma unroll
        for (int ki = 0; ki < 2; ++ki) {
            uint32_t a[2][4];
            #pragma unroll
            for (int mi = 0; mi < 2; ++mi) {
                int r  = wm + mi * 16 + (lane & 15);
                int cc = ki * 16 + (lane >> 4) * 8;
                ldsm_x4(a[mi], smem_u32(&As[cur][r][cc]));
            }
            uint32_t b[4][4];
            #pragma unroll
            for (int nn = 0; nn < 4; ++nn) {
                int rr = ki * 16 + (lane & 7) + ((lane >> 3) & 1) * 8;
                int cc = wn + nn * 16 + (lane >> 4) * 8;
                ldsm_x4t(b[nn], smem_u32(&Bs[cur][rr][cc]));
            }
            #pragma unroll
            for (int mi = 0; mi < 2; ++mi)
                #pragma unroll
                for (int ni = 0; ni < 8; ++ni)
                    mma_bf16(c[mi][ni], a[mi],
                             b[ni >> 1][(ni & 1) * 2], b[ni >> 1][(ni & 1) * 2 + 1]);
        }

        if (kt + 1 < nk) sts_tile((kt + 1) & 1);
        __syncthreads();
    }

    // epilogue
    const int g  = lane >> 2;
    const int t4 = lane & 3;
    const float* bp = bias + (size_t)e * NDIM;

    // per-thread row metadata (4 rows: mi in {0,1} x h in {0,1})
    int   rtok[4]; bool rval[4]; float rcorr[4];
    #pragma unroll
    for (int mi = 0; mi < 2; ++mi)
        #pragma unroll
        for (int h = 0; h < 2; ++h) {
            const int r = wm + mi * 16 + g + h * 8;
            const int q = mi * 2 + h;
            rval[q] = (m0 + r < cnt);
            rtok[q] = toks[r];
            rcorr[q] = FFN1 ? 0.5f * g_xsum[rtok[q]] : g_score[rtok[q]];
        }

    #pragma unroll
    for (int mi = 0; mi < 2; ++mi) {
        #pragma unroll
        for (int ni = 0; ni < 8; ++ni) {
            const int ncol = n0 + wn + ni * 8 + t4 * 2;
            const float b0v = bp[ncol];
            const float b1v = bp[ncol + 1];
            #pragma unroll
            for (int h = 0; h < 2; ++h) {
                const int q = mi * 2 + h;
                if (rval[q]) {
                    const int tok = rtok[q];
                    if (FFN1) {
                        float v0 = gelu_exact(c[mi][ni][h * 2 + 0] + b0v + rcorr[q]);
                        float v1 = gelu_exact(c[mi][ni][h * 2 + 1] + b1v + rcorr[q]);
                        *reinterpret_cast<__nv_bfloat162*>(
                            &g_h[(size_t)tok * HDIM + ncol]) =
                            __floats2bfloat162_rn(v0, v1);
                    } else {
                        const float s = rcorr[q];
                        float2 o;
                        o.x = (c[mi][ni][h * 2 + 0] + b0v) * s;
                        o.y = (c[mi][ni][h * 2 + 1] + b1v) * s;
                        *reinterpret_cast<float2*>(
                            &out[(size_t)tok * CDIM + ncol]) = o;
                    }
                }
            }
        }
    }
}

// ---------------- launch ----------------
extern "C" void kernel_launch(void* const* d_in, const int* in_sizes, int n_in,
                              void* d_out, int out_size) {
    (void)in_sizes; (void)n_in; (void)out_size;
    const float* x  = (const float*)d_in[0];
    const float* Wr = (const float*)d_in[1];
    const float* wg = (const float*)d_in[2];
    const float* W1 = (const float*)d_in[3];
    const float* b1 = (const float*)d_in[4];
    const float* W2 = (const float*)d_in[5];
    const float* b2 = (const float*)d_in[6];
    float* out = (float*)d_out;

    zero_cnt_kernel<<<1, 32>>>();
    route_kernel<<<NTOK / (4 * 8), 256>>>(x, Wr, wg);
    moe_gemm<CDIM, HDIM, true ><<<dim3(HDIM / BN, NTOK / BM, NEXP), 256>>>(W1, b1, nullptr);
    moe_gemm<HDIM, CDIM, false><<<dim3(CDIM / BN, NTOK / BM, NEXP), 256>>>(W2, b2, out);
}

// round 5
// speedup vs baseline: 1.4105x; 1.4105x over previous
#include <cuda_runtime.h>
#include <cuda_bf16.h>
#include <cstdint>
#include <math.h>

#define NTOK 8192
#define CDIM 1024
#define HDIM 2048
#define NEXP 8

#define BM 128
#define BN 256
#define BK 64            // bf16 elements per k-tile (128 bytes per row)
#define STAGES 3

// ---------------- device scratch (no allocations allowed) ----------------
__device__ __nv_bfloat16 g_xb[(size_t)NTOK * CDIM];            // x bf16
__device__ __nv_bfloat16 g_h [(size_t)NTOK * HDIM];            // hidden bf16
__device__ __nv_bfloat16 g_w1t[(size_t)NEXP * HDIM * CDIM];    // (W1-0.5)^T [e][n][k]
__device__ __nv_bfloat16 g_w2t[(size_t)NEXP * CDIM * HDIM];    // W2^T      [e][n][k]
__device__ int   g_tok[NEXP * NTOK];
__device__ int   g_cnt[NEXP];
__device__ float g_score[NTOK];
__device__ float g_xsum[NTOK];

// ---------------- helpers ----------------
__device__ __forceinline__ uint32_t smem_u32(const void* p) {
    return static_cast<uint32_t>(__cvta_generic_to_shared(p));
}
__device__ __forceinline__ void ldsm_x4(uint32_t r[4], uint32_t addr) {
    asm volatile("ldmatrix.sync.aligned.m8n8.x4.shared.b16 {%0,%1,%2,%3}, [%4];"
                 : "=r"(r[0]), "=r"(r[1]), "=r"(r[2]), "=r"(r[3]) : "r"(addr));
}
__device__ __forceinline__ void mma_bf16(float c[4], const uint32_t a[4],
                                         uint32_t b0, uint32_t b1) {
    asm volatile(
        "mma.sync.aligned.m16n8k16.row.col.f32.bf16.bf16.f32 "
        "{%0,%1,%2,%3}, {%4,%5,%6,%7}, {%8,%9}, {%0,%1,%2,%3};\n"
        : "+f"(c[0]), "+f"(c[1]), "+f"(c[2]), "+f"(c[3])
        : "r"(a[0]), "r"(a[1]), "r"(a[2]), "r"(a[3]), "r"(b0), "r"(b1));
}
__device__ __forceinline__ void cpa16(uint32_t dst, const void* src) {
    asm volatile("cp.async.cg.shared.global [%0], [%1], 16;" :: "r"(dst), "l"(src) : "memory");
}
__device__ __forceinline__ void cpa_commit() {
    asm volatile("cp.async.commit_group;" ::: "memory");
}
__device__ __forceinline__ void cpa_wait1() {
    asm volatile("cp.async.wait_group 1;" ::: "memory");
}
__device__ __forceinline__ float gelu_exact(float v) {
    return 0.5f * v * (1.0f + erff(v * 0.70710678118654752f));
}

// ---------------- kernel 0: zero bucket counters ----------------
__global__ void zero_cnt_kernel() {
    if (threadIdx.x < NEXP) g_cnt[threadIdx.x] = 0;
}

// ---------------- kernel 1: routing (validated) ----------------
__global__ __launch_bounds__(256) void route_kernel(
    const float* __restrict__ x, const float* __restrict__ Wr,
    const float* __restrict__ wg)
{
    __shared__ float wgn_s[NEXP][16];
    const int tid = threadIdx.x;
    if (tid < NEXP) {
        float row[16];
        float nrm = 0.f;
        #pragma unroll
        for (int j = 0; j < 16; ++j) { row[j] = wg[tid * 16 + j]; nrm += row[j] * row[j]; }
        nrm = fmaxf(sqrtf(nrm), 1e-4f);
        #pragma unroll
        for (int j = 0; j < 16; ++j) wgn_s[tid][j] = row[j] / nrm;
    }
    __syncthreads();

    const int lane = tid & 31;
    const int gw   = (blockIdx.x * blockDim.x + tid) >> 5;
    const int t0   = gw * 4;

    float acc[4][16];
    float sx[4] = {0.f, 0.f, 0.f, 0.f};
    #pragma unroll
    for (int ti = 0; ti < 4; ++ti)
        #pragma unroll
        for (int j = 0; j < 16; ++j) acc[ti][j] = 0.f;

    for (int c = 0; c < 32; ++c) {
        const int k = c * 32 + lane;
        float wr[16];
        #pragma unroll
        for (int j = 0; j < 16; ++j) wr[j] = Wr[j * CDIM + k];
        #pragma unroll
        for (int ti = 0; ti < 4; ++ti) {
            float xv = x[(size_t)(t0 + ti) * CDIM + k];
            g_xb[(size_t)(t0 + ti) * CDIM + k] = __float2bfloat16(xv);
            sx[ti] += xv;
            #pragma unroll
            for (int j = 0; j < 16; ++j) acc[ti][j] = fmaf(xv, wr[j], acc[ti][j]);
        }
    }
    #pragma unroll
    for (int ti = 0; ti < 4; ++ti) {
        #pragma unroll
        for (int j = 0; j < 16; ++j)
            #pragma unroll
            for (int off = 16; off > 0; off >>= 1)
                acc[ti][j] += __shfl_xor_sync(0xffffffffu, acc[ti][j], off);
        #pragma unroll
        for (int off = 16; off > 0; off >>= 1)
            sx[ti] += __shfl_xor_sync(0xffffffffu, sx[ti], off);
    }

    if (lane < 4) {
        const int t = t0 + lane;
        float logit[NEXP];
        float best = -1e30f; int be = 0;
        #pragma unroll
        for (int e = 0; e < NEXP; ++e) {
            float l = 0.f;
            #pragma unroll
            for (int j = 0; j < 16; ++j) l += acc[lane][j] * wgn_s[e][j];
            logit[e] = l;
            if (l > best) { best = l; be = e; }
        }
        float denom = 0.f;
        #pragma unroll
        for (int e = 0; e < NEXP; ++e) denom += expf(logit[e] - best);
        g_score[t] = 1.0f / denom;
        g_xsum[t]  = sx[lane];
        int pos = atomicAdd(&g_cnt[be], 1);
        g_tok[be * NTOK + pos] = t;
    }
}

// ---------------- kernel 2: weight convert + transpose ----------------
// Wt[e][n][k] = bf16(W[e][k][n] - shift)
template<bool W1SEL>
__global__ __launch_bounds__(256) void convert_w(const float* __restrict__ W) {
    __shared__ float t[64][65];
    const int K = W1SEL ? CDIM : HDIM;
    const int N = W1SEL ? HDIM : CDIM;
    __nv_bfloat16* Wt = W1SEL ? g_w1t : g_w2t;
    const float shift = W1SEL ? 0.5f : 0.0f;
    const int e = blockIdx.z;
    const int k0 = blockIdx.x * 64, n0 = blockIdx.y * 64;
    const int c = threadIdx.x & 63, r4 = threadIdx.x >> 6;
    const float* Wp = W + (size_t)e * K * N;
    #pragma unroll
    for (int i = 0; i < 16; ++i) {
        int row = i * 4 + r4;
        t[row][c] = Wp[(size_t)(k0 + row) * N + n0 + c];
    }
    __syncthreads();
    __nv_bfloat16* Wo = Wt + (size_t)e * N * K;
    #pragma unroll
    for (int i = 0; i < 16; ++i) {
        int nrow = i * 4 + r4;
        Wo[(size_t)(n0 + nrow) * K + k0 + c] = __float2bfloat16(t[c][nrow] - shift);
    }
}

// ---------------- kernel 3/4: grouped GEMM, bf16 mma.sync + cp.async -----
// smem: [0..512) toks, [512..1024) cs, [1024..2048) bs,
//       [2048 + s*49152): A tile 16KB (128 x 128B, XOR-swizzled) + B tile 32KB
#define TILE0       2048
#define STAGE_BYTES 49152
#define A_BYTES     16384
#define SMEM_TOTAL  (TILE0 + STAGES * STAGE_BYTES)

template<int KDIM, int NDIM, bool FFN1>
__global__ __launch_bounds__(256, 1) void moe_gemm2(
    const float* __restrict__ bias, float* __restrict__ out)
{
    const int e   = blockIdx.z;
    const int cnt = g_cnt[e];
    const int m0  = blockIdx.y * BM;
    if (m0 >= cnt) return;
    const int n0  = blockIdx.x * BN;

    extern __shared__ __align__(1024) char smem[];
    int*   toks = (int*)(smem);
    float* cs   = (float*)(smem + 512);
    float* bs   = (float*)(smem + 1024);
    const uint32_t tiles = smem_u32(smem + TILE0);

    const int tid = threadIdx.x, lane = tid & 31, wid = tid >> 5;

    if (tid < BM) {
        const int tk = g_tok[e * NTOK + min(m0 + tid, cnt - 1)];
        toks[tid] = tk;
        cs[tid]   = FFN1 ? 0.5f * g_xsum[tk] : g_score[tk];
    }
    bs[tid] = bias[(size_t)e * NDIM + n0 + tid];
    __syncthreads();

    // ---- staging setup: thread -> (chunk = 16B column, rows rbase+32i) ----
    const __nv_bfloat16* __restrict__ A  = FFN1 ? g_xb  : g_h;
    const __nv_bfloat16* __restrict__ Wt = (FFN1 ? g_w1t : g_w2t) + (size_t)e * NDIM * KDIM;
    const int chunk = tid & 7;
    const int rbase = tid >> 3;                      // 0..31
    const uint32_t sw    = (uint32_t)((chunk ^ (rbase & 7)) * 16);
    const uint32_t roff0 = (uint32_t)(rbase * 128) + sw;
    const __nv_bfloat16* aptr[4];
    #pragma unroll
    for (int i = 0; i < 4; ++i)
        aptr[i] = A + (size_t)toks[rbase + i * 32] * KDIM + chunk * 8;
    const __nv_bfloat16* bptr0 = Wt + (size_t)(n0 + rbase) * KDIM + chunk * 8;

    auto load_tile = [&](int t, int s) {
        const uint32_t sa = tiles + s * STAGE_BYTES;
        const uint32_t sb = sa + A_BYTES;
        const int ke = t * BK;
        #pragma unroll
        for (int i = 0; i < 4; ++i)
            cpa16(sa + roff0 + i * 4096, aptr[i] + ke);
        #pragma unroll
        for (int i = 0; i < 8; ++i)
            cpa16(sb + roff0 + i * 4096, bptr0 + (size_t)i * 32 * KDIM + ke);
        cpa_commit();
    };

    // ---- warp tiling: 2 (M) x 4 (N) warps, warp tile 64x64 ----
    const int wm = (wid & 1) * 64;
    const int wn = (wid >> 1) * 64;
    const int lane15 = lane & 15;
    const int laneh  = lane >> 4;

    uint32_t arow128[4], arow7[4], brow128[4], brow7[4];
    #pragma unroll
    for (int i = 0; i < 4; ++i) {
        const int ra = wm + i * 16 + lane15;
        arow128[i] = (uint32_t)(ra * 128); arow7[i] = (uint32_t)(ra & 7);
        const int rb = wn + i * 16 + lane15;
        brow128[i] = (uint32_t)(rb * 128); brow7[i] = (uint32_t)(rb & 7);
    }

    float c[4][8][4];
    #pragma unroll
    for (int mi = 0; mi < 4; ++mi)
        #pragma unroll
        for (int ni = 0; ni < 8; ++ni)
            #pragma unroll
            for (int q = 0; q < 4; ++q) c[mi][ni][q] = 0.f;

    const int T = KDIM / BK;
    load_tile(0, 0);
    load_tile(1, 1);

    for (int t = 0; t < T; ++t) {
        const int s = t % STAGES;
        cpa_wait1();
        __syncthreads();
        if (t + 2 < T) load_tile(t + 2, (t + 2) % STAGES);
        else cpa_commit();                 // keep group accounting uniform

        const uint32_t Ab = tiles + s * STAGE_BYTES;
        const uint32_t Bb = Ab + A_BYTES;
        #pragma unroll
        for (int ki = 0; ki < 4; ++ki) {
            const uint32_t ck = (uint32_t)(ki * 2 + laneh);
            uint32_t a[4][4], b[4][4];
            #pragma unroll
            for (int i = 0; i < 4; ++i)
                ldsm_x4(a[i], Ab + arow128[i] + ((ck ^ arow7[i]) << 4));
            #pragma unroll
            for (int i = 0; i < 4; ++i)
                ldsm_x4(b[i], Bb + brow128[i] + ((ck ^ brow7[i]) << 4));
            #pragma unroll
            for (int mi = 0; mi < 4; ++mi)
                #pragma unroll
                for (int n8 = 0; n8 < 8; ++n8) {
                    const int ni = n8 >> 1, o = n8 & 1;
                    mma_bf16(c[mi][n8], a[mi], b[ni][o], b[ni][o + 2]);
                }
        }
    }

    // ---------------- epilogue ----------------
    const int g  = lane >> 2;
    const int t4 = lane & 3;
    #pragma unroll
    for (int mi = 0; mi < 4; ++mi) {
        #pragma unroll
        for (int h = 0; h < 2; ++h) {
            const int r = wm + mi * 16 + g + h * 8;
            if (m0 + r < cnt) {
                const int   tok  = toks[r];
                const float corr = cs[r];
                #pragma unroll
                for (int n8 = 0; n8 < 8; ++n8) {
                    const int col = wn + n8 * 8 + t4 * 2;
                    const float v0 = c[mi][n8][h * 2 + 0] + bs[col];
                    const float v1 = c[mi][n8][h * 2 + 1] + bs[col + 1];
                    if (FFN1) {
                        *reinterpret_cast<__nv_bfloat162*>(
                            &g_h[(size_t)tok * HDIM + n0 + col]) =
                            __floats2bfloat162_rn(gelu_exact(v0 + corr),
                                                  gelu_exact(v1 + corr));
                    } else {
                        float2 o2;
                        o2.x = v0 * corr;
                        o2.y = v1 * corr;
                        *reinterpret_cast<float2*>(
                            &out[(size_t)tok * CDIM + n0 + col]) = o2;
                    }
                }
            }
        }
    }
}

// ---------------- launch ----------------
extern "C" void kernel_launch(void* const* d_in, const int* in_sizes, int n_in,
                              void* d_out, int out_size) {
    (void)in_sizes; (void)n_in; (void)out_size;
    const float* x  = (const float*)d_in[0];
    const float* Wr = (const float*)d_in[1];
    const float* wg = (const float*)d_in[2];
    const float* W1 = (const float*)d_in[3];
    const float* b1 = (const float*)d_in[4];
    const float* W2 = (const float*)d_in[5];
    const float* b2 = (const float*)d_in[6];
    float* out = (float*)d_out;

    cudaFuncSetAttribute(moe_gemm2<CDIM, HDIM, true>,
                         cudaFuncAttributeMaxDynamicSharedMemorySize, SMEM_TOTAL);
    cudaFuncSetAttribute(moe_gemm2<HDIM, CDIM, false>,
                         cudaFuncAttributeMaxDynamicSharedMemorySize, SMEM_TOTAL);

    zero_cnt_kernel<<<1, 32>>>();
    convert_w<true ><<<dim3(CDIM / 64, HDIM / 64, NEXP), 256>>>(W1);
    convert_w<false><<<dim3(HDIM / 64, CDIM / 64, NEXP), 256>>>(W2);
    route_kernel<<<NTOK / (4 * 8), 256>>>(x, Wr, wg);
    moe_gemm2<CDIM, HDIM, true ><<<dim3(HDIM / BN, NTOK / BM, NEXP), 256, SMEM_TOTAL>>>(b1, nullptr);
    moe_gemm2<HDIM, CDIM, false><<<dim3(CDIM / BN, NTOK / BM, NEXP), 256, SMEM_TOTAL>>>(b2, out);
}

// round 8
// speedup vs baseline: 1.4193x; 1.0063x over previous
#include <cuda_runtime.h>
#include <cuda_bf16.h>
#include <cstdint>
#include <math.h>

#define NTOK 8192
#define CDIM 1024
#define HDIM 2048
#define NEXP 8

#define BM 128
#define BN 256
#define BK 64            // bf16 elements per k-tile (128 bytes per row)
#define STAGES 3

// ---------------- device scratch (no allocations allowed) ----------------
__device__ __nv_bfloat16 g_xb[(size_t)NTOK * CDIM];            // x bf16
__device__ __nv_bfloat16 g_h [(size_t)NTOK * HDIM];            // hidden bf16
__device__ __nv_bfloat16 g_w1t[(size_t)NEXP * HDIM * CDIM];    // (W1-0.5)^T [e][n][k]
__device__ __nv_bfloat16 g_w2t[(size_t)NEXP * CDIM * HDIM];    // W2^T      [e][n][k]
__device__ int   g_tok[NEXP * NTOK];
__device__ int   g_cnt[NEXP];
__device__ float g_score[NTOK];
__device__ float g_xsum[NTOK];

// ---------------- helpers ----------------
__device__ __forceinline__ uint32_t smem_u32(const void* p) {
    return static_cast<uint32_t>(__cvta_generic_to_shared(p));
}
__device__ __forceinline__ void ldsm_x4(uint32_t r[4], uint32_t addr) {
    asm volatile("ldmatrix.sync.aligned.m8n8.x4.shared.b16 {%0,%1,%2,%3}, [%4];"
                 : "=r"(r[0]), "=r"(r[1]), "=r"(r[2]), "=r"(r[3]) : "r"(addr));
}
__device__ __forceinline__ void mma_bf16(float c[4], const uint32_t a[4],
                                         uint32_t b0, uint32_t b1) {
    asm volatile(
        "mma.sync.aligned.m16n8k16.row.col.f32.bf16.bf16.f32 "
        "{%0,%1,%2,%3}, {%4,%5,%6,%7}, {%8,%9}, {%0,%1,%2,%3};\n"
        : "+f"(c[0]), "+f"(c[1]), "+f"(c[2]), "+f"(c[3])
        : "r"(a[0]), "r"(a[1]), "r"(a[2]), "r"(a[3]), "r"(b0), "r"(b1));
}
__device__ __forceinline__ void cpa16(uint32_t dst, const void* src) {
    asm volatile("cp.async.cg.shared.global [%0], [%1], 16;" :: "r"(dst), "l"(src) : "memory");
}
__device__ __forceinline__ void cpa_commit() {
    asm volatile("cp.async.commit_group;" ::: "memory");
}
__device__ __forceinline__ void cpa_wait1() {
    asm volatile("cp.async.wait_group 1;" ::: "memory");
}
__device__ __forceinline__ float gelu_exact(float v) {
    return 0.5f * v * (1.0f + erff(v * 0.70710678118654752f));
}

// ---------------- kernel 0: zero bucket counters ----------------
__global__ void zero_cnt_kernel() {
    if (threadIdx.x < NEXP) g_cnt[threadIdx.x] = 0;
}

// ---------------- kernel 1: routing (validated) ----------------
__global__ __launch_bounds__(256) void route_kernel(
    const float* __restrict__ x, const float* __restrict__ Wr,
    const float* __restrict__ wg)
{
    __shared__ float wgn_s[NEXP][16];
    const int tid = threadIdx.x;
    if (tid < NEXP) {
        float row[16];
        float nrm = 0.f;
        #pragma unroll
        for (int j = 0; j < 16; ++j) { row[j] = wg[tid * 16 + j]; nrm += row[j] * row[j]; }
        nrm = fmaxf(sqrtf(nrm), 1e-4f);
        #pragma unroll
        for (int j = 0; j < 16; ++j) wgn_s[tid][j] = row[j] / nrm;
    }
    __syncthreads();

    const int lane = tid & 31;
    const int gw   = (blockIdx.x * blockDim.x + tid) >> 5;
    const int t0   = gw * 4;

    float acc[4][16];
    float sx[4] = {0.f, 0.f, 0.f, 0.f};
    #pragma unroll
    for (int ti = 0; ti < 4; ++ti)
        #pragma unroll
        for (int j = 0; j < 16; ++j) acc[ti][j] = 0.f;

    for (int c = 0; c < 32; ++c) {
        const int k = c * 32 + lane;
        float wr[16];
        #pragma unroll
        for (int j = 0; j < 16; ++j) wr[j] = Wr[j * CDIM + k];
        #pragma unroll
        for (int ti = 0; ti < 4; ++ti) {
            float xv = x[(size_t)(t0 + ti) * CDIM + k];
            g_xb[(size_t)(t0 + ti) * CDIM + k] = __float2bfloat16(xv);
            sx[ti] += xv;
            #pragma unroll
            for (int j = 0; j < 16; ++j) acc[ti][j] = fmaf(xv, wr[j], acc[ti][j]);
        }
    }
    #pragma unroll
    for (int ti = 0; ti < 4; ++ti) {
        #pragma unroll
        for (int j = 0; j < 16; ++j)
            #pragma unroll
            for (int off = 16; off > 0; off >>= 1)
                acc[ti][j] += __shfl_xor_sync(0xffffffffu, acc[ti][j], off);
        #pragma unroll
        for (int off = 16; off > 0; off >>= 1)
            sx[ti] += __shfl_xor_sync(0xffffffffu, sx[ti], off);
    }

    if (lane < 4) {
        const int t = t0 + lane;
        float logit[NEXP];
        float best = -1e30f; int be = 0;
        #pragma unroll
        for (int e = 0; e < NEXP; ++e) {
            float l = 0.f;
            #pragma unroll
            for (int j = 0; j < 16; ++j) l += acc[lane][j] * wgn_s[e][j];
            logit[e] = l;
            if (l > best) { best = l; be = e; }
        }
        float denom = 0.f;
        #pragma unroll
        for (int e = 0; e < NEXP; ++e) denom += expf(logit[e] - best);
        g_score[t] = 1.0f / denom;
        g_xsum[t]  = sx[lane];
        int pos = atomicAdd(&g_cnt[be], 1);
        g_tok[be * NTOK + pos] = t;
    }
}

// ---------------- kernel 2: weight convert + transpose (vectorized) ------
// Wt[e][n][k] = bf16(W[e][k][n] - shift); separate launches per weight
// (same grid/launch structure as the validated R5 kernel; only the body
//  is vectorized: float4 loads, uint4 stores)
template<bool W1SEL>
__global__ __launch_bounds__(256) void convert_w(const float* __restrict__ W) {
    __shared__ float tb[64 * 65];
    const int K = W1SEL ? CDIM : HDIM;
    const int N = W1SEL ? HDIM : CDIM;
    __nv_bfloat16* Wt = W1SEL ? g_w1t : g_w2t;
    const float shift = W1SEL ? 0.5f : 0.0f;
    const int e = blockIdx.z;
    const int k0 = blockIdx.x * 64, n0 = blockIdx.y * 64;
    const int tid = threadIdx.x;
    const float* Wp = W + (size_t)e * K * N;

    // load 64x64 fp32 tile with float4 (4 iters x 256 threads x 16B)
    #pragma unroll
    for (int p = 0; p < 4; ++p) {
        const int idx = tid + p * 256;     // float4 index 0..1023
        const int row = idx >> 4;          // k row 0..63
        const int c4  = (idx & 15) * 4;    // n col
        const float4 v = *reinterpret_cast<const float4*>(
            &Wp[(size_t)(k0 + row) * N + n0 + c4]);
        float* d = &tb[row * 65 + c4];
        d[0] = v.x; d[1] = v.y; d[2] = v.z; d[3] = v.w;
    }
    __syncthreads();

    // store transposed as bf16 with uint4 (2 iters x 256 threads x 16B)
    __nv_bfloat16* Wo = Wt + (size_t)e * N * K;
    #pragma unroll
    for (int p = 0; p < 2; ++p) {
        const int idx = tid + p * 256;     // uint4 index 0..511
        const int nrow = idx >> 3;         // n row 0..63
        const int kseg = (idx & 7) * 8;    // k segment (8 bf16 = 16B)
        __nv_bfloat162 b[4];
        #pragma unroll
        for (int j = 0; j < 4; ++j)
            b[j] = __floats2bfloat162_rn(tb[(kseg + 2*j    ) * 65 + nrow] - shift,
                                         tb[(kseg + 2*j + 1) * 65 + nrow] - shift);
        *reinterpret_cast<uint4*>(&Wo[(size_t)(n0 + nrow) * K + k0 + kseg]) =
            *reinterpret_cast<const uint4*>(b);
    }
}

// ---------------- grouped GEMM, bf16 mma.sync + cp.async (R5-validated) --
#define TILE0       2048
#define STAGE_BYTES 49152
#define A_BYTES     16384
#define SMEM_TOTAL  (TILE0 + STAGES * STAGE_BYTES)

template<int KDIM, int NDIM, bool FFN1>
__global__ __launch_bounds__(256, 1) void moe_gemm2(
    const float* __restrict__ bias, float* __restrict__ out)
{
    const int e   = blockIdx.z;
    const int cnt = g_cnt[e];
    const int m0  = blockIdx.y * BM;
    if (m0 >= cnt) return;
    const int n0  = blockIdx.x * BN;

    extern __shared__ __align__(1024) char smem[];
    int*   toks = (int*)(smem);
    float* cs   = (float*)(smem + 512);
    float* bs   = (float*)(smem + 1024);
    const uint32_t tiles = smem_u32(smem + TILE0);

    const int tid = threadIdx.x, lane = tid & 31, wid = tid >> 5;

    if (tid < BM) {
        const int tk = g_tok[e * NTOK + min(m0 + tid, cnt - 1)];
        toks[tid] = tk;
        cs[tid]   = FFN1 ? 0.5f * g_xsum[tk] : g_score[tk];
    }
    bs[tid] = bias[(size_t)e * NDIM + n0 + tid];
    __syncthreads();

    // ---- staging: thread -> (16B chunk, rows rbase+32i), XOR swizzle ----
    const __nv_bfloat16* __restrict__ A  = FFN1 ? g_xb  : g_h;
    const __nv_bfloat16* __restrict__ Wt = (FFN1 ? g_w1t : g_w2t) + (size_t)e * NDIM * KDIM;
    const int chunk = tid & 7;
    const int rbase = tid >> 3;                      // 0..31
    const uint32_t sw    = (uint32_t)((chunk ^ (rbase & 7)) * 16);
    const uint32_t roff0 = (uint32_t)(rbase * 128) + sw;
    const __nv_bfloat16* aptr[4];
    #pragma unroll
    for (int i = 0; i < 4; ++i)
        aptr[i] = A + (size_t)toks[rbase + i * 32] * KDIM + chunk * 8;
    const __nv_bfloat16* bptr0 = Wt + (size_t)(n0 + rbase) * KDIM + chunk * 8;

    auto load_tile = [&](int t, int s) {
        const uint32_t sa = tiles + s * STAGE_BYTES;
        const uint32_t sb = sa + A_BYTES;
        const int ke = t * BK;
        #pragma unroll
        for (int i = 0; i < 4; ++i)
            cpa16(sa + roff0 + i * 4096, aptr[i] + ke);
        #pragma unroll
        for (int i = 0; i < 8; ++i)
            cpa16(sb + roff0 + i * 4096, bptr0 + (size_t)i * 32 * KDIM + ke);
        cpa_commit();
    };

    // ---- warp tiling: 2 (M) x 4 (N) warps, warp tile 64x64 ----
    const int wm = (wid & 1) * 64;
    const int wn = (wid >> 1) * 64;
    const int lane15 = lane & 15;
    const int laneh  = lane >> 4;

    uint32_t arow128[4], arow7[4], brow128[4], brow7[4];
    #pragma unroll
    for (int i = 0; i < 4; ++i) {
        const int ra = wm + i * 16 + lane15;
        arow128[i] = (uint32_t)(ra * 128); arow7[i] = (uint32_t)(ra & 7);
        const int rb = wn + i * 16 + lane15;
        brow128[i] = (uint32_t)(rb * 128); brow7[i] = (uint32_t)(rb & 7);
    }

    float c[4][8][4];
    #pragma unroll
    for (int mi = 0; mi < 4; ++mi)
        #pragma unroll
        for (int ni = 0; ni < 8; ++ni)
            #pragma unroll
            for (int q = 0; q < 4; ++q) c[mi][ni][q] = 0.f;

    const int T = KDIM / BK;
    load_tile(0, 0);
    load_tile(1, 1);

    for (int t = 0; t < T; ++t) {
        const int s = t % STAGES;
        cpa_wait1();
        __syncthreads();
        if (t + 2 < T) load_tile(t + 2, (t + 2) % STAGES);
        else cpa_commit();                 // keep group accounting uniform

        const uint32_t Ab = tiles + s * STAGE_BYTES;
        const uint32_t Bb = Ab + A_BYTES;
        #pragma unroll
        for (int ki = 0; ki < 4; ++ki) {
            const uint32_t ck = (uint32_t)(ki * 2 + laneh);
            uint32_t a[4][4], b[4][4];
            #pragma unroll
            for (int i = 0; i < 4; ++i)
                ldsm_x4(a[i], Ab + arow128[i] + ((ck ^ arow7[i]) << 4));
            #pragma unroll
            for (int i = 0; i < 4; ++i)
                ldsm_x4(b[i], Bb + brow128[i] + ((ck ^ brow7[i]) << 4));
            #pragma unroll
            for (int mi = 0; mi < 4; ++mi)
                #pragma unroll
                for (int n8 = 0; n8 < 8; ++n8) {
                    const int ni = n8 >> 1, o = n8 & 1;
                    mma_bf16(c[mi][n8], a[mi], b[ni][o], b[ni][o + 2]);
                }
        }
    }

    // ---------------- epilogue ----------------
    const int g  = lane >> 2;
    const int t4 = lane & 3;
    #pragma unroll
    for (int mi = 0; mi < 4; ++mi) {
        #pragma unroll
        for (int h = 0; h < 2; ++h) {
            const int r = wm + mi * 16 + g + h * 8;
            if (m0 + r < cnt) {
                const int   tok  = toks[r];
                const float corr = cs[r];
                #pragma unroll
                for (int n8 = 0; n8 < 8; ++n8) {
                    const int col = wn + n8 * 8 + t4 * 2;
                    const float v0 = c[mi][n8][h * 2 + 0] + bs[col];
                    const float v1 = c[mi][n8][h * 2 + 1] + bs[col + 1];
                    if (FFN1) {
                        *reinterpret_cast<__nv_bfloat162*>(
                            &g_h[(size_t)tok * HDIM + n0 + col]) =
                            __floats2bfloat162_rn(gelu_exact(v0 + corr),
                                                  gelu_exact(v1 + corr));
                    } else {
                        float2 o2;
                        o2.x = v0 * corr;
                        o2.y = v1 * corr;
                        *reinterpret_cast<float2*>(
                            &out[(size_t)tok * CDIM + n0 + col]) = o2;
                    }
                }
            }
        }
    }
}

// ---------------- launch ----------------
extern "C" void kernel_launch(void* const* d_in, const int* in_sizes, int n_in,
                              void* d_out, int out_size) {
    (void)in_sizes; (void)n_in; (void)out_size;
    const float* x  = (const float*)d_in[0];
    const float* Wr = (const float*)d_in[1];
    const float* wg = (const float*)d_in[2];
    const float* W1 = (const float*)d_in[3];
    const float* b1 = (const float*)d_in[4];
    const float* W2 = (const float*)d_in[5];
    const float* b2 = (const float*)d_in[6];
    float* out = (float*)d_out;

    cudaFuncSetAttribute(moe_gemm2<CDIM, HDIM, true>,
                         cudaFuncAttributeMaxDynamicSharedMemorySize, SMEM_TOTAL);
    cudaFuncSetAttribute(moe_gemm2<HDIM, CDIM, false>,
                         cudaFuncAttributeMaxDynamicSharedMemorySize, SMEM_TOTAL);

    zero_cnt_kernel<<<1, 32>>>();
    convert_w<true ><<<dim3(CDIM / 64, HDIM / 64, NEXP), 256>>>(W1);
    convert_w<false><<<dim3(HDIM / 64, CDIM / 64, NEXP), 256>>>(W2);
    route_kernel<<<NTOK / (4 * 8), 256>>>(x, Wr, wg);
    moe_gemm2<CDIM, HDIM, true ><<<dim3(HDIM / BN, NTOK / BM, NEXP), 256, SMEM_TOTAL>>>(b1, nullptr);
    moe_gemm2<HDIM, CDIM, false><<<dim3(CDIM / BN, NTOK / BM, NEXP), 256, SMEM_TOTAL>>>(b2, out);
}

// round 11
// speedup vs baseline: 1.4459x; 1.0187x over previous
#include <cuda_runtime.h>
#include <cuda_bf16.h>
#include <cstdint>
#include <math.h>

#define NTOK 8192
#define CDIM 1024
#define HDIM 2048
#define NEXP 8

#define BM 128
#define BN 256
#define BK 64            // bf16 elements per k-tile (128 bytes per row)
#define STAGES 3

// ---------------- device scratch (no allocations allowed) ----------------
__device__ __nv_bfloat16 g_xb[(size_t)NTOK * CDIM];            // x bf16
__device__ __nv_bfloat16 g_h [(size_t)NTOK * HDIM];            // hidden bf16
__device__ __nv_bfloat16 g_w1t[(size_t)NEXP * HDIM * CDIM];    // (W1-0.5)^T [e][n][k]
__device__ __nv_bfloat16 g_w2t[(size_t)NEXP * CDIM * HDIM];    // W2^T      [e][n][k]
__device__ int   g_tok[NEXP * NTOK];
__device__ int   g_cnt[NEXP];
__device__ float g_score[NTOK];
__device__ float g_xsum[NTOK];

// ---------------- helpers ----------------
__device__ __forceinline__ uint32_t smem_u32(const void* p) {
    return static_cast<uint32_t>(__cvta_generic_to_shared(p));
}
__device__ __forceinline__ void ldsm_x4(uint32_t r[4], uint32_t addr) {
    asm volatile("ldmatrix.sync.aligned.m8n8.x4.shared.b16 {%0,%1,%2,%3}, [%4];"
                 : "=r"(r[0]), "=r"(r[1]), "=r"(r[2]), "=r"(r[3]) : "r"(addr));
}
__device__ __forceinline__ void mma_bf16(float c[4], const uint32_t a[4],
                                         uint32_t b0, uint32_t b1) {
    asm volatile(
        "mma.sync.aligned.m16n8k16.row.col.f32.bf16.bf16.f32 "
        "{%0,%1,%2,%3}, {%4,%5,%6,%7}, {%8,%9}, {%0,%1,%2,%3};\n"
        : "+f"(c[0]), "+f"(c[1]), "+f"(c[2]), "+f"(c[3])
        : "r"(a[0]), "r"(a[1]), "r"(a[2]), "r"(a[3]), "r"(b0), "r"(b1));
}
__device__ __forceinline__ void cpa16(uint32_t dst, const void* src) {
    asm volatile("cp.async.cg.shared.global [%0], [%1], 16;" :: "r"(dst), "l"(src) : "memory");
}
__device__ __forceinline__ void cpa_commit() {
    asm volatile("cp.async.commit_group;" ::: "memory");
}
__device__ __forceinline__ void cpa_wait1() {
    asm volatile("cp.async.wait_group 1;" ::: "memory");
}
__device__ __forceinline__ float gelu_exact(float v) {
    return 0.5f * v * (1.0f + erff(v * 0.70710678118654752f));
}

// ---------------- kernel 0: zero bucket counters ----------------
__global__ void zero_cnt_kernel() {
    if (threadIdx.x < NEXP) g_cnt[threadIdx.x] = 0;
}

// ---------------- kernel 1: routing (bit-identical math, 2x MLP) ---------
// k-loop unrolled by 2: loads for both halves batched (8 x-LDGs in flight),
// FMA order kept exactly as the sequential loop -> bit-identical results.
__global__ __launch_bounds__(256) void route_kernel(
    const float* __restrict__ x, const float* __restrict__ Wr,
    const float* __restrict__ wg)
{
    __shared__ float wgn_s[NEXP][16];
    const int tid = threadIdx.x;
    if (tid < NEXP) {
        float row[16];
        float nrm = 0.f;
        #pragma unroll
        for (int j = 0; j < 16; ++j) { row[j] = wg[tid * 16 + j]; nrm += row[j] * row[j]; }
        nrm = fmaxf(sqrtf(nrm), 1e-4f);
        #pragma unroll
        for (int j = 0; j < 16; ++j) wgn_s[tid][j] = row[j] / nrm;
    }
    __syncthreads();

    const int lane = tid & 31;
    const int gw   = (blockIdx.x * blockDim.x + tid) >> 5;
    const int t0   = gw * 4;

    float acc[4][16];
    float sx[4] = {0.f, 0.f, 0.f, 0.f};
    #pragma unroll
    for (int ti = 0; ti < 4; ++ti)
        #pragma unroll
        for (int j = 0; j < 16; ++j) acc[ti][j] = 0.f;

    for (int c = 0; c < 32; c += 2) {
        const int kA = c * 32 + lane;
        const int kB = kA + 32;
        // batched loads (independent -> MLP = 8 x-loads in flight)
        float wrA[16], wrB[16];
        #pragma unroll
        for (int j = 0; j < 16; ++j) wrA[j] = Wr[j * CDIM + kA];
        #pragma unroll
        for (int j = 0; j < 16; ++j) wrB[j] = Wr[j * CDIM + kB];
        float xvA[4], xvB[4];
        #pragma unroll
        for (int ti = 0; ti < 4; ++ti) {
            xvA[ti] = x[(size_t)(t0 + ti) * CDIM + kA];
            xvB[ti] = x[(size_t)(t0 + ti) * CDIM + kB];
        }
        #pragma unroll
        for (int ti = 0; ti < 4; ++ti) {
            g_xb[(size_t)(t0 + ti) * CDIM + kA] = __float2bfloat16(xvA[ti]);
            g_xb[(size_t)(t0 + ti) * CDIM + kB] = __float2bfloat16(xvB[ti]);
        }
        // FMA order identical to the sequential loop: first c, then c+1
        #pragma unroll
        for (int ti = 0; ti < 4; ++ti) {
            sx[ti] += xvA[ti];
            #pragma unroll
            for (int j = 0; j < 16; ++j) acc[ti][j] = fmaf(xvA[ti], wrA[j], acc[ti][j]);
        }
        #pragma unroll
        for (int ti = 0; ti < 4; ++ti) {
            sx[ti] += xvB[ti];
            #pragma unroll
            for (int j = 0; j < 16; ++j) acc[ti][j] = fmaf(xvB[ti], wrB[j], acc[ti][j]);
        }
    }
    #pragma unroll
    for (int ti = 0; ti < 4; ++ti) {
        #pragma unroll
        for (int j = 0; j < 16; ++j)
            #pragma unroll
            for (int off = 16; off > 0; off >>= 1)
                acc[ti][j] += __shfl_xor_sync(0xffffffffu, acc[ti][j], off);
        #pragma unroll
        for (int off = 16; off > 0; off >>= 1)
            sx[ti] += __shfl_xor_sync(0xffffffffu, sx[ti], off);
    }

    if (lane < 4) {
        const int t = t0 + lane;
        float logit[NEXP];
        float best = -1e30f; int be = 0;
        #pragma unroll
        for (int e = 0; e < NEXP; ++e) {
            float l = 0.f;
            #pragma unroll
            for (int j = 0; j < 16; ++j) l += acc[lane][j] * wgn_s[e][j];
            logit[e] = l;
            if (l > best) { best = l; be = e; }
        }
        float denom = 0.f;
        #pragma unroll
        for (int e = 0; e < NEXP; ++e) denom += expf(logit[e] - best);
        g_score[t] = 1.0f / denom;
        g_xsum[t]  = sx[lane];
        int pos = atomicAdd(&g_cnt[be], 1);
        g_tok[be * NTOK + pos] = t;
    }
}

// ---------------- kernel 2: weight convert + transpose (validated R8) ----
template<bool W1SEL>
__global__ __launch_bounds__(256) void convert_w(const float* __restrict__ W) {
    __shared__ float tb[64 * 65];
    const int K = W1SEL ? CDIM : HDIM;
    const int N = W1SEL ? HDIM : CDIM;
    __nv_bfloat16* Wt = W1SEL ? g_w1t : g_w2t;
    const float shift = W1SEL ? 0.5f : 0.0f;
    const int e = blockIdx.z;
    const int k0 = blockIdx.x * 64, n0 = blockIdx.y * 64;
    const int tid = threadIdx.x;
    const float* Wp = W + (size_t)e * K * N;

    #pragma unroll
    for (int p = 0; p < 4; ++p) {
        const int idx = tid + p * 256;
        const int row = idx >> 4;
        const int c4  = (idx & 15) * 4;
        const float4 v = *reinterpret_cast<const float4*>(
            &Wp[(size_t)(k0 + row) * N + n0 + c4]);
        float* d = &tb[row * 65 + c4];
        d[0] = v.x; d[1] = v.y; d[2] = v.z; d[3] = v.w;
    }
    __syncthreads();

    __nv_bfloat16* Wo = Wt + (size_t)e * N * K;
    #pragma unroll
    for (int p = 0; p < 2; ++p) {
        const int idx = tid + p * 256;
        const int nrow = idx >> 3;
        const int kseg = (idx & 7) * 8;
        __nv_bfloat162 b[4];
        #pragma unroll
        for (int j = 0; j < 4; ++j)
            b[j] = __floats2bfloat162_rn(tb[(kseg + 2*j    ) * 65 + nrow] - shift,
                                         tb[(kseg + 2*j + 1) * 65 + nrow] - shift);
        *reinterpret_cast<uint4*>(&Wo[(size_t)(n0 + nrow) * K + k0 + kseg]) =
            *reinterpret_cast<const uint4*>(b);
    }
}

// ---------------- grouped GEMM, bf16 mma.sync + cp.async (R8-validated) --
#define TILE0       2048
#define STAGE_BYTES 49152
#define A_BYTES     16384
#define SMEM_TOTAL  (TILE0 + STAGES * STAGE_BYTES)

template<int KDIM, int NDIM, bool FFN1>
__global__ __launch_bounds__(256, 1) void moe_gemm2(
    const float* __restrict__ bias, float* __restrict__ out)
{
    const int e   = blockIdx.z;
    const int cnt = g_cnt[e];
    const int m0  = blockIdx.y * BM;
    if (m0 >= cnt) return;
    const int n0  = blockIdx.x * BN;

    extern __shared__ __align__(1024) char smem[];
    int*   toks = (int*)(smem);
    float* cs   = (float*)(smem + 512);
    float* bs   = (float*)(smem + 1024);
    const uint32_t tiles = smem_u32(smem + TILE0);

    const int tid = threadIdx.x, lane = tid & 31, wid = tid >> 5;

    if (tid < BM) {
        const int tk = g_tok[e * NTOK + min(m0 + tid, cnt - 1)];
        toks[tid] = tk;
        cs[tid]   = FFN1 ? 0.5f * g_xsum[tk] : g_score[tk];
    }
    bs[tid] = bias[(size_t)e * NDIM + n0 + tid];
    __syncthreads();

    // ---- staging: thread -> (16B chunk, rows rbase+32i), XOR swizzle ----
    const __nv_bfloat16* __restrict__ A  = FFN1 ? g_xb  : g_h;
    const __nv_bfloat16* __restrict__ Wt = (FFN1 ? g_w1t : g_w2t) + (size_t)e * NDIM * KDIM;
    const int chunk = tid & 7;
    const int rbase = tid >> 3;                      // 0..31
    const uint32_t sw    = (uint32_t)((chunk ^ (rbase & 7)) * 16);
    const uint32_t roff0 = (uint32_t)(rbase * 128) + sw;
    const __nv_bfloat16* aptr[4];
    #pragma unroll
    for (int i = 0; i < 4; ++i)
        aptr[i] = A + (size_t)toks[rbase + i * 32] * KDIM + chunk * 8;
    const __nv_bfloat16* bptr0 = Wt + (size_t)(n0 + rbase) * KDIM + chunk * 8;

    auto load_tile = [&](int t, int s) {
        const uint32_t sa = tiles + s * STAGE_BYTES;
        const uint32_t sb = sa + A_BYTES;
        const int ke = t * BK;
        #pragma unroll
        for (int i = 0; i < 4; ++i)
            cpa16(sa + roff0 + i * 4096, aptr[i] + ke);
        #pragma unroll
        for (int i = 0; i < 8; ++i)
            cpa16(sb + roff0 + i * 4096, bptr0 + (size_t)i * 32 * KDIM + ke);
        cpa_commit();
    };

    // ---- warp tiling: 2 (M) x 4 (N) warps, warp tile 64x64 ----
    const int wm = (wid & 1) * 64;
    const int wn = (wid >> 1) * 64;
    const int lane15 = lane & 15;
    const int laneh  = lane >> 4;

    uint32_t arow128[4], arow7[4], brow128[4], brow7[4];
    #pragma unroll
    for (int i = 0; i < 4; ++i) {
        const int ra = wm + i * 16 + lane15;
        arow128[i] = (uint32_t)(ra * 128); arow7[i] = (uint32_t)(ra & 7);
        const int rb = wn + i * 16 + lane15;
        brow128[i] = (uint32_t)(rb * 128); brow7[i] = (uint32_t)(rb & 7);
    }

    float c[4][8][4];
    #pragma unroll
    for (int mi = 0; mi < 4; ++mi)
        #pragma unroll
        for (int ni = 0; ni < 8; ++ni)
            #pragma unroll
            for (int q = 0; q < 4; ++q) c[mi][ni][q] = 0.f;

    const int T = KDIM / BK;
    load_tile(0, 0);
    load_tile(1, 1);

    for (int t = 0; t < T; ++t) {
        const int s = t % STAGES;
        cpa_wait1();
        __syncthreads();
        if (t + 2 < T) load_tile(t + 2, (t + 2) % STAGES);
        else cpa_commit();                 // keep group accounting uniform

        const uint32_t Ab = tiles + s * STAGE_BYTES;
        const uint32_t Bb = Ab + A_BYTES;
        #pragma unroll
        for (int ki = 0; ki < 4; ++ki) {
            const uint32_t ck = (uint32_t)(ki * 2 + laneh);
            uint32_t a[4][4], b[4][4];
            #pragma unroll
            for (int i = 0; i < 4; ++i)
                ldsm_x4(a[i], Ab + arow128[i] + ((ck ^ arow7[i]) << 4));
            #pragma unroll
            for (int i = 0; i < 4; ++i)
                ldsm_x4(b[i], Bb + brow128[i] + ((ck ^ brow7[i]) << 4));
            #pragma unroll
            for (int mi = 0; mi < 4; ++mi)
                #pragma unroll
                for (int n8 = 0; n8 < 8; ++n8) {
                    const int ni = n8 >> 1, o = n8 & 1;
                    mma_bf16(c[mi][n8], a[mi], b[ni][o], b[ni][o + 2]);
                }
        }
    }

    // ---------------- epilogue ----------------
    const int g  = lane >> 2;
    const int t4 = lane & 3;
    #pragma unroll
    for (int mi = 0; mi < 4; ++mi) {
        #pragma unroll
        for (int h = 0; h < 2; ++h) {
            const int r = wm + mi * 16 + g + h * 8;
            if (m0 + r < cnt) {
                const int   tok  = toks[r];
                const float corr = cs[r];
                #pragma unroll
                for (int n8 = 0; n8 < 8; ++n8) {
                    const int col = wn + n8 * 8 + t4 * 2;
                    const float v0 = c[mi][n8][h * 2 + 0] + bs[col];
                    const float v1 = c[mi][n8][h * 2 + 1] + bs[col + 1];
                    if (FFN1) {
                        *reinterpret_cast<__nv_bfloat162*>(
                            &g_h[(size_t)tok * HDIM + n0 + col]) =
                            __floats2bfloat162_rn(gelu_exact(v0 + corr),
                                                  gelu_exact(v1 + corr));
                    } else {
                        float2 o2;
                        o2.x = v0 * corr;
                        o2.y = v1 * corr;
                        *reinterpret_cast<float2*>(
                            &out[(size_t)tok * CDIM + n0 + col]) = o2;
                    }
                }
            }
        }
    }
}

// ---------------- launch ----------------
extern "C" void kernel_launch(void* const* d_in, const int* in_sizes, int n_in,
                              void* d_out, int out_size) {
    (void)in_sizes; (void)n_in; (void)out_size;
    const float* x  = (const float*)d_in[0];
    const float* Wr = (const float*)d_in[1];
    const float* wg = (const float*)d_in[2];
    const float* W1 = (const float*)d_in[3];
    const float* b1 = (const float*)d_in[4];
    const float* W2 = (const float*)d_in[5];
    const float* b2 = (const float*)d_in[6];
    float* out = (float*)d_out;

    cudaFuncSetAttribute(moe_gemm2<CDIM, HDIM, true>,
                         cudaFuncAttributeMaxDynamicSharedMemorySize, SMEM_TOTAL);
    cudaFuncSetAttribute(moe_gemm2<HDIM, CDIM, false>,
                         cudaFuncAttributeMaxDynamicSharedMemorySize, SMEM_TOTAL);

    zero_cnt_kernel<<<1, 32>>>();
    convert_w<true ><<<dim3(CDIM / 64, HDIM / 64, NEXP), 256>>>(W1);
    convert_w<false><<<dim3(HDIM / 64, CDIM / 64, NEXP), 256>>>(W2);
    route_kernel<<<NTOK / (4 * 8), 256>>>(x, Wr, wg);
    moe_gemm2<CDIM, HDIM, true ><<<dim3(HDIM / BN, NTOK / BM, NEXP), 256, SMEM_TOTAL>>>(b1, nullptr);
    moe_gemm2<HDIM, CDIM, false><<<dim3(CDIM / BN, NTOK / BM, NEXP), 256, SMEM_TOTAL>>>(b2, out);
}

// round 12
// speedup vs baseline: 1.4822x; 1.0251x over previous
#include <cuda_runtime.h>
#include <cuda_bf16.h>
#include <cstdint>
#include <math.h>

#define NTOK 8192
#define CDIM 1024
#define HDIM 2048
#define NEXP 8

#define BM 128
#define BN 256
#define BK 64            // bf16 elements per k-tile (128 bytes per row)
#define STAGES 3

// ---------------- device scratch (no allocations allowed) ----------------
__device__ __nv_bfloat16 g_xb[(size_t)NTOK * CDIM];            // x bf16
__device__ __nv_bfloat16 g_h [(size_t)NTOK * HDIM];            // hidden bf16
__device__ __nv_bfloat16 g_w1t[(size_t)NEXP * HDIM * CDIM];    // (W1-0.5)^T [e][n][k]
__device__ __nv_bfloat16 g_w2t[(size_t)NEXP * CDIM * HDIM];    // W2^T      [e][n][k]
__device__ int   g_tok[NEXP * NTOK];
__device__ int   g_cnt[NEXP];
__device__ float g_score[NTOK];
__device__ float g_xsum[NTOK];

// ---------------- helpers ----------------
__device__ __forceinline__ uint32_t smem_u32(const void* p) {
    return static_cast<uint32_t>(__cvta_generic_to_shared(p));
}
__device__ __forceinline__ void ldsm_x4(uint32_t r[4], uint32_t addr) {
    asm volatile("ldmatrix.sync.aligned.m8n8.x4.shared.b16 {%0,%1,%2,%3}, [%4];"
                 : "=r"(r[0]), "=r"(r[1]), "=r"(r[2]), "=r"(r[3]) : "r"(addr));
}
__device__ __forceinline__ void mma_bf16(float c[4], const uint32_t a[4],
                                         uint32_t b0, uint32_t b1) {
    asm volatile(
        "mma.sync.aligned.m16n8k16.row.col.f32.bf16.bf16.f32 "
        "{%0,%1,%2,%3}, {%4,%5,%6,%7}, {%8,%9}, {%0,%1,%2,%3};\n"
        : "+f"(c[0]), "+f"(c[1]), "+f"(c[2]), "+f"(c[3])
        : "r"(a[0]), "r"(a[1]), "r"(a[2]), "r"(a[3]), "r"(b0), "r"(b1));
}
__device__ __forceinline__ void cpa16(uint32_t dst, const void* src) {
    asm volatile("cp.async.cg.shared.global [%0], [%1], 16;" :: "r"(dst), "l"(src) : "memory");
}
__device__ __forceinline__ void cpa_commit() {
    asm volatile("cp.async.commit_group;" ::: "memory");
}
__device__ __forceinline__ void cpa_wait1() {
    asm volatile("cp.async.wait_group 1;" ::: "memory");
}
__device__ __forceinline__ float gelu_exact(float v) {
    return 0.5f * v * (1.0f + erff(v * 0.70710678118654752f));
}

// ---------------- kernel 0: zero bucket counters ----------------
__global__ void zero_cnt_kernel() {
    if (threadIdx.x < NEXP) g_cnt[threadIdx.x] = 0;
}

// ---------------- kernel 1: routing (validated R11) ----------------
__global__ __launch_bounds__(256) void route_kernel(
    const float* __restrict__ x, const float* __restrict__ Wr,
    const float* __restrict__ wg)
{
    __shared__ float wgn_s[NEXP][16];
    const int tid = threadIdx.x;
    if (tid < NEXP) {
        float row[16];
        float nrm = 0.f;
        #pragma unroll
        for (int j = 0; j < 16; ++j) { row[j] = wg[tid * 16 + j]; nrm += row[j] * row[j]; }
        nrm = fmaxf(sqrtf(nrm), 1e-4f);
        #pragma unroll
        for (int j = 0; j < 16; ++j) wgn_s[tid][j] = row[j] / nrm;
    }
    __syncthreads();

    const int lane = tid & 31;
    const int gw   = (blockIdx.x * blockDim.x + tid) >> 5;
    const int t0   = gw * 4;

    float acc[4][16];
    float sx[4] = {0.f, 0.f, 0.f, 0.f};
    #pragma unroll
    for (int ti = 0; ti < 4; ++ti)
        #pragma unroll
        for (int j = 0; j < 16; ++j) acc[ti][j] = 0.f;

    for (int c = 0; c < 32; c += 2) {
        const int kA = c * 32 + lane;
        const int kB = kA + 32;
        float wrA[16], wrB[16];
        #pragma unroll
        for (int j = 0; j < 16; ++j) wrA[j] = Wr[j * CDIM + kA];
        #pragma unroll
        for (int j = 0; j < 16; ++j) wrB[j] = Wr[j * CDIM + kB];
        float xvA[4], xvB[4];
        #pragma unroll
        for (int ti = 0; ti < 4; ++ti) {
            xvA[ti] = x[(size_t)(t0 + ti) * CDIM + kA];
            xvB[ti] = x[(size_t)(t0 + ti) * CDIM + kB];
        }
        #pragma unroll
        for (int ti = 0; ti < 4; ++ti) {
            g_xb[(size_t)(t0 + ti) * CDIM + kA] = __float2bfloat16(xvA[ti]);
            g_xb[(size_t)(t0 + ti) * CDIM + kB] = __float2bfloat16(xvB[ti]);
        }
        #pragma unroll
        for (int ti = 0; ti < 4; ++ti) {
            sx[ti] += xvA[ti];
            #pragma unroll
            for (int j = 0; j < 16; ++j) acc[ti][j] = fmaf(xvA[ti], wrA[j], acc[ti][j]);
        }
        #pragma unroll
        for (int ti = 0; ti < 4; ++ti) {
            sx[ti] += xvB[ti];
            #pragma unroll
            for (int j = 0; j < 16; ++j) acc[ti][j] = fmaf(xvB[ti], wrB[j], acc[ti][j]);
        }
    }
    #pragma unroll
    for (int ti = 0; ti < 4; ++ti) {
        #pragma unroll
        for (int j = 0; j < 16; ++j)
            #pragma unroll
            for (int off = 16; off > 0; off >>= 1)
                acc[ti][j] += __shfl_xor_sync(0xffffffffu, acc[ti][j], off);
        #pragma unroll
        for (int off = 16; off > 0; off >>= 1)
            sx[ti] += __shfl_xor_sync(0xffffffffu, sx[ti], off);
    }

    if (lane < 4) {
        const int t = t0 + lane;
        float logit[NEXP];
        float best = -1e30f; int be = 0;
        #pragma unroll
        for (int e = 0; e < NEXP; ++e) {
            float l = 0.f;
            #pragma unroll
            for (int j = 0; j < 16; ++j) l += acc[lane][j] * wgn_s[e][j];
            logit[e] = l;
            if (l > best) { best = l; be = e; }
        }
        float denom = 0.f;
        #pragma unroll
        for (int e = 0; e < NEXP; ++e) denom += expf(logit[e] - best);
        g_score[t] = 1.0f / denom;
        g_xsum[t]  = sx[lane];
        int pos = atomicAdd(&g_cnt[be], 1);
        g_tok[be * NTOK + pos] = t;
    }
}

// ---------------- kernel 2: weight convert + transpose (validated R8) ----
template<bool W1SEL>
__global__ __launch_bounds__(256) void convert_w(const float* __restrict__ W) {
    __shared__ float tb[64 * 65];
    const int K = W1SEL ? CDIM : HDIM;
    const int N = W1SEL ? HDIM : CDIM;
    __nv_bfloat16* Wt = W1SEL ? g_w1t : g_w2t;
    const float shift = W1SEL ? 0.5f : 0.0f;
    const int e = blockIdx.z;
    const int k0 = blockIdx.x * 64, n0 = blockIdx.y * 64;
    const int tid = threadIdx.x;
    const float* Wp = W + (size_t)e * K * N;

    #pragma unroll
    for (int p = 0; p < 4; ++p) {
        const int idx = tid + p * 256;
        const int row = idx >> 4;
        const int c4  = (idx & 15) * 4;
        const float4 v = *reinterpret_cast<const float4*>(
            &Wp[(size_t)(k0 + row) * N + n0 + c4]);
        float* d = &tb[row * 65 + c4];
        d[0] = v.x; d[1] = v.y; d[2] = v.z; d[3] = v.w;
    }
    __syncthreads();

    __nv_bfloat16* Wo = Wt + (size_t)e * N * K;
    #pragma unroll
    for (int p = 0; p < 2; ++p) {
        const int idx = tid + p * 256;
        const int nrow = idx >> 3;
        const int kseg = (idx & 7) * 8;
        __nv_bfloat162 b[4];
        #pragma unroll
        for (int j = 0; j < 4; ++j)
            b[j] = __floats2bfloat162_rn(tb[(kseg + 2*j    ) * 65 + nrow] - shift,
                                         tb[(kseg + 2*j + 1) * 65 + nrow] - shift);
        *reinterpret_cast<uint4*>(&Wo[(size_t)(n0 + nrow) * K + k0 + kseg]) =
            *reinterpret_cast<const uint4*>(b);
    }
}

// ---------------- grouped GEMM, bf16 mma.sync + cp.async (R8-validated) --
#define TILE0       2048
#define STAGE_BYTES 49152
#define A_BYTES     16384
#define SMEM_TOTAL  (TILE0 + STAGES * STAGE_BYTES)

template<int KDIM, int NDIM, bool FFN1>
__global__ __launch_bounds__(256, 1) void moe_gemm2(
    const float* __restrict__ bias, float* __restrict__ out)
{
    const int e   = blockIdx.z;
    const int cnt = g_cnt[e];
    const int m0  = blockIdx.y * BM;
    if (m0 >= cnt) return;
    const int n0  = blockIdx.x * BN;

    extern __shared__ __align__(1024) char smem[];
    int*   toks = (int*)(smem);
    float* cs   = (float*)(smem + 512);
    float* bs   = (float*)(smem + 1024);
    const uint32_t tiles = smem_u32(smem + TILE0);

    const int tid = threadIdx.x, lane = tid & 31, wid = tid >> 5;

    if (tid < BM) {
        const int tk = g_tok[e * NTOK + min(m0 + tid, cnt - 1)];
        toks[tid] = tk;
        cs[tid]   = FFN1 ? 0.5f * g_xsum[tk] : g_score[tk];
    }
    bs[tid] = bias[(size_t)e * NDIM + n0 + tid];
    __syncthreads();

    // ---- staging: thread -> (16B chunk, rows rbase+32i), XOR swizzle ----
    const __nv_bfloat16* __restrict__ A  = FFN1 ? g_xb  : g_h;
    const __nv_bfloat16* __restrict__ Wt = (FFN1 ? g_w1t : g_w2t) + (size_t)e * NDIM * KDIM;
    const int chunk = tid & 7;
    const int rbase = tid >> 3;                      // 0..31
    const uint32_t sw    = (uint32_t)((chunk ^ (rbase & 7)) * 16);
    const uint32_t roff0 = (uint32_t)(rbase * 128) + sw;
    const __nv_bfloat16* aptr[4];
    #pragma unroll
    for (int i = 0; i < 4; ++i)
        aptr[i] = A + (size_t)toks[rbase + i * 32] * KDIM + chunk * 8;
    const __nv_bfloat16* bptr0 = Wt + (size_t)(n0 + rbase) * KDIM + chunk * 8;

    auto load_tile = [&](int t, int s) {
        const uint32_t sa = tiles + s * STAGE_BYTES;
        const uint32_t sb = sa + A_BYTES;
        const int ke = t * BK;
        #pragma unroll
        for (int i = 0; i < 4; ++i)
            cpa16(sa + roff0 + i * 4096, aptr[i] + ke);
        #pragma unroll
        for (int i = 0; i < 8; ++i)
            cpa16(sb + roff0 + i * 4096, bptr0 + (size_t)i * 32 * KDIM + ke);
        cpa_commit();
    };

    // ---- warp tiling: 2 (M) x 4 (N) warps, warp tile 64x64 ----
    const int wm = (wid & 1) * 64;
    const int wn = (wid >> 1) * 64;
    const int lane15 = lane & 15;
    const int laneh  = lane >> 4;

    uint32_t arow128[4], arow7[4], brow128[4], brow7[4];
    #pragma unroll
    for (int i = 0; i < 4; ++i) {
        const int ra = wm + i * 16 + lane15;
        arow128[i] = (uint32_t)(ra * 128); arow7[i] = (uint32_t)(ra & 7);
        const int rb = wn + i * 16 + lane15;
        brow128[i] = (uint32_t)(rb * 128); brow7[i] = (uint32_t)(rb & 7);
    }

    float c[4][8][4];
    #pragma unroll
    for (int mi = 0; mi < 4; ++mi)
        #pragma unroll
        for (int ni = 0; ni < 8; ++ni)
            #pragma unroll
            for (int q = 0; q < 4; ++q) c[mi][ni][q] = 0.f;

    const int T = KDIM / BK;
    load_tile(0, 0);
    load_tile(1, 1);

    for (int t = 0; t < T; ++t) {
        const int s = t % STAGES;
        cpa_wait1();
        __syncthreads();
        if (t + 2 < T) load_tile(t + 2, (t + 2) % STAGES);
        else cpa_commit();                 // keep group accounting uniform

        const uint32_t Ab = tiles + s * STAGE_BYTES;
        const uint32_t Bb = Ab + A_BYTES;
        #pragma unroll
        for (int ki = 0; ki < 4; ++ki) {
            const uint32_t ck = (uint32_t)(ki * 2 + laneh);
            uint32_t a[4][4], b[4][4];
            #pragma unroll
            for (int i = 0; i < 4; ++i)
                ldsm_x4(a[i], Ab + arow128[i] + ((ck ^ arow7[i]) << 4));
            #pragma unroll
            for (int i = 0; i < 4; ++i)
                ldsm_x4(b[i], Bb + brow128[i] + ((ck ^ brow7[i]) << 4));
            #pragma unroll
            for (int mi = 0; mi < 4; ++mi)
                #pragma unroll
                for (int n8 = 0; n8 < 8; ++n8) {
                    const int ni = n8 >> 1, o = n8 & 1;
                    mma_bf16(c[mi][n8], a[mi], b[ni][o], b[ni][o + 2]);
                }
        }
    }

    // ---------------- epilogue ----------------
    const int g  = lane >> 2;
    const int t4 = lane & 3;
    #pragma unroll
    for (int mi = 0; mi < 4; ++mi) {
        #pragma unroll
        for (int h = 0; h < 2; ++h) {
            const int r = wm + mi * 16 + g + h * 8;
            if (m0 + r < cnt) {
                const int   tok  = toks[r];
                const float corr = cs[r];
                #pragma unroll
                for (int n8 = 0; n8 < 8; ++n8) {
                    const int col = wn + n8 * 8 + t4 * 2;
                    const float v0 = c[mi][n8][h * 2 + 0] + bs[col];
                    const float v1 = c[mi][n8][h * 2 + 1] + bs[col + 1];
                    if (FFN1) {
                        *reinterpret_cast<__nv_bfloat162*>(
                            &g_h[(size_t)tok * HDIM + n0 + col]) =
                            __floats2bfloat162_rn(gelu_exact(v0 + corr),
                                                  gelu_exact(v1 + corr));
                    } else {
                        float2 o2;
                        o2.x = v0 * corr;
                        o2.y = v1 * corr;
                        *reinterpret_cast<float2*>(
                            &out[(size_t)tok * CDIM + n0 + col]) = o2;
                    }
                }
            }
        }
    }
}

// ---------------- launch: fork/join stream topology ----------------
// main: zero -> convW1 -> (wait route) FFN1 -> (wait convW2) FFN2
// side: (wait zero) route -> convW2
// route || convW1 (disjoint outputs); convW2 || FFN1 (disjoint).
extern "C" void kernel_launch(void* const* d_in, const int* in_sizes, int n_in,
                              void* d_out, int out_size) {
    (void)in_sizes; (void)n_in; (void)out_size;
    const float* x  = (const float*)d_in[0];
    const float* Wr = (const float*)d_in[1];
    const float* wg = (const float*)d_in[2];
    const float* W1 = (const float*)d_in[3];
    const float* b1 = (const float*)d_in[4];
    const float* W2 = (const float*)d_in[5];
    const float* b2 = (const float*)d_in[6];
    float* out = (float*)d_out;

    cudaFuncSetAttribute(moe_gemm2<CDIM, HDIM, true>,
                         cudaFuncAttributeMaxDynamicSharedMemorySize, SMEM_TOTAL);
    cudaFuncSetAttribute(moe_gemm2<HDIM, CDIM, false>,
                         cudaFuncAttributeMaxDynamicSharedMemorySize, SMEM_TOTAL);

    cudaStream_t s2;
    cudaStreamCreateWithFlags(&s2, cudaStreamNonBlocking);
    cudaEvent_t evZero, evRoute, evConv2;
    cudaEventCreateWithFlags(&evZero,  cudaEventDisableTiming);
    cudaEventCreateWithFlags(&evRoute, cudaEventDisableTiming);
    cudaEventCreateWithFlags(&evConv2, cudaEventDisableTiming);

    // main stream (legacy default, as in all prior validated runs)
    zero_cnt_kernel<<<1, 32>>>();
    cudaEventRecord(evZero, 0);

    // side stream: route, then convW2
    cudaStreamWaitEvent(s2, evZero, 0);
    route_kernel<<<NTOK / (4 * 8), 256, 0, s2>>>(x, Wr, wg);
    cudaEventRecord(evRoute, s2);
    convert_w<false><<<dim3(HDIM / 64, CDIM / 64, NEXP), 256, 0, s2>>>(W2);
    cudaEventRecord(evConv2, s2);

    // main stream: convW1 runs concurrent with route
    convert_w<true ><<<dim3(CDIM / 64, HDIM / 64, NEXP), 256>>>(W1);
    cudaStreamWaitEvent(0, evRoute, 0);
    moe_gemm2<CDIM, HDIM, true ><<<dim3(HDIM / BN, NTOK / BM, NEXP), 256, SMEM_TOTAL>>>(b1, nullptr);
    cudaStreamWaitEvent(0, evConv2, 0);
    moe_gemm2<HDIM, CDIM, false><<<dim3(CDIM / BN, NTOK / BM, NEXP), 256, SMEM_TOTAL>>>(b2, out);

    cudaEventDestroy(evZero);
    cudaEventDestroy(evRoute);
    cudaEventDestroy(evConv2);
    cudaStreamDestroy(s2);
}

// round 13
// speedup vs baseline: 1.5331x; 1.0344x over previous
#include <cuda_runtime.h>
#include <cuda_bf16.h>
#include <cstdint>
#include <math.h>

#define NTOK 8192
#define CDIM 1024
#define HDIM 2048
#define NEXP 8

#define BM 128
#define BN 128
#define BK 64            // bf16 elements per k-tile (128 bytes per row)
#define STAGES 3

// ---------------- device scratch (no allocations allowed) ----------------
__device__ __nv_bfloat16 g_xb[(size_t)NTOK * CDIM];            // x bf16
__device__ __nv_bfloat16 g_h [(size_t)NTOK * HDIM];            // hidden bf16
__device__ __nv_bfloat16 g_w1t[(size_t)NEXP * HDIM * CDIM];    // (W1-0.5)^T [e][n][k]
__device__ __nv_bfloat16 g_w2t[(size_t)NEXP * CDIM * HDIM];    // W2^T      [e][n][k]
__device__ int   g_tok[NEXP * NTOK];
__device__ int   g_cnt[NEXP];
__device__ float g_score[NTOK];
__device__ float g_xsum[NTOK];

// ---------------- helpers ----------------
__device__ __forceinline__ uint32_t smem_u32(const void* p) {
    return static_cast<uint32_t>(__cvta_generic_to_shared(p));
}
__device__ __forceinline__ void ldsm_x4(uint32_t r[4], uint32_t addr) {
    asm volatile("ldmatrix.sync.aligned.m8n8.x4.shared.b16 {%0,%1,%2,%3}, [%4];"
                 : "=r"(r[0]), "=r"(r[1]), "=r"(r[2]), "=r"(r[3]) : "r"(addr));
}
__device__ __forceinline__ void mma_bf16(float c[4], const uint32_t a[4],
                                         uint32_t b0, uint32_t b1) {
    asm volatile(
        "mma.sync.aligned.m16n8k16.row.col.f32.bf16.bf16.f32 "
        "{%0,%1,%2,%3}, {%4,%5,%6,%7}, {%8,%9}, {%0,%1,%2,%3};\n"
        : "+f"(c[0]), "+f"(c[1]), "+f"(c[2]), "+f"(c[3])
        : "r"(a[0]), "r"(a[1]), "r"(a[2]), "r"(a[3]), "r"(b0), "r"(b1));
}
__device__ __forceinline__ void cpa16(uint32_t dst, const void* src) {
    asm volatile("cp.async.cg.shared.global [%0], [%1], 16;" :: "r"(dst), "l"(src) : "memory");
}
__device__ __forceinline__ void cpa_commit() {
    asm volatile("cp.async.commit_group;" ::: "memory");
}
__device__ __forceinline__ void cpa_wait1() {
    asm volatile("cp.async.wait_group 1;" ::: "memory");
}
__device__ __forceinline__ float gelu_exact(float v) {
    return 0.5f * v * (1.0f + erff(v * 0.70710678118654752f));
}

// ---------------- kernel 0: zero bucket counters ----------------
__global__ void zero_cnt_kernel() {
    if (threadIdx.x < NEXP) g_cnt[threadIdx.x] = 0;
}

// ---------------- kernel 1: routing (validated R11) ----------------
__global__ __launch_bounds__(256) void route_kernel(
    const float* __restrict__ x, const float* __restrict__ Wr,
    const float* __restrict__ wg)
{
    __shared__ float wgn_s[NEXP][16];
    const int tid = threadIdx.x;
    if (tid < NEXP) {
        float row[16];
        float nrm = 0.f;
        #pragma unroll
        for (int j = 0; j < 16; ++j) { row[j] = wg[tid * 16 + j]; nrm += row[j] * row[j]; }
        nrm = fmaxf(sqrtf(nrm), 1e-4f);
        #pragma unroll
        for (int j = 0; j < 16; ++j) wgn_s[tid][j] = row[j] / nrm;
    }
    __syncthreads();

    const int lane = tid & 31;
    const int gw   = (blockIdx.x * blockDim.x + tid) >> 5;
    const int t0   = gw * 4;

    float acc[4][16];
    float sx[4] = {0.f, 0.f, 0.f, 0.f};
    #pragma unroll
    for (int ti = 0; ti < 4; ++ti)
        #pragma unroll
        for (int j = 0; j < 16; ++j) acc[ti][j] = 0.f;

    for (int c = 0; c < 32; c += 2) {
        const int kA = c * 32 + lane;
        const int kB = kA + 32;
        float wrA[16], wrB[16];
        #pragma unroll
        for (int j = 0; j < 16; ++j) wrA[j] = Wr[j * CDIM + kA];
        #pragma unroll
        for (int j = 0; j < 16; ++j) wrB[j] = Wr[j * CDIM + kB];
        float xvA[4], xvB[4];
        #pragma unroll
        for (int ti = 0; ti < 4; ++ti) {
            xvA[ti] = x[(size_t)(t0 + ti) * CDIM + kA];
            xvB[ti] = x[(size_t)(t0 + ti) * CDIM + kB];
        }
        #pragma unroll
        for (int ti = 0; ti < 4; ++ti) {
            g_xb[(size_t)(t0 + ti) * CDIM + kA] = __float2bfloat16(xvA[ti]);
            g_xb[(size_t)(t0 + ti) * CDIM + kB] = __float2bfloat16(xvB[ti]);
        }
        #pragma unroll
        for (int ti = 0; ti < 4; ++ti) {
            sx[ti] += xvA[ti];
            #pragma unroll
            for (int j = 0; j < 16; ++j) acc[ti][j] = fmaf(xvA[ti], wrA[j], acc[ti][j]);
        }
        #pragma unroll
        for (int ti = 0; ti < 4; ++ti) {
            sx[ti] += xvB[ti];
            #pragma unroll
            for (int j = 0; j < 16; ++j) acc[ti][j] = fmaf(xvB[ti], wrB[j], acc[ti][j]);
        }
    }
    #pragma unroll
    for (int ti = 0; ti < 4; ++ti) {
        #pragma unroll
        for (int j = 0; j < 16; ++j)
            #pragma unroll
            for (int off = 16; off > 0; off >>= 1)
                acc[ti][j] += __shfl_xor_sync(0xffffffffu, acc[ti][j], off);
        #pragma unroll
        for (int off = 16; off > 0; off >>= 1)
            sx[ti] += __shfl_xor_sync(0xffffffffu, sx[ti], off);
    }

    if (lane < 4) {
        const int t = t0 + lane;
        float logit[NEXP];
        float best = -1e30f; int be = 0;
        #pragma unroll
        for (int e = 0; e < NEXP; ++e) {
            float l = 0.f;
            #pragma unroll
            for (int j = 0; j < 16; ++j) l += acc[lane][j] * wgn_s[e][j];
            logit[e] = l;
            if (l > best) { best = l; be = e; }
        }
        float denom = 0.f;
        #pragma unroll
        for (int e = 0; e < NEXP; ++e) denom += expf(logit[e] - best);
        g_score[t] = 1.0f / denom;
        g_xsum[t]  = sx[lane];
        int pos = atomicAdd(&g_cnt[be], 1);
        g_tok[be * NTOK + pos] = t;
    }
}

// ---------------- kernel 2: weight convert + transpose (validated R8) ----
template<bool W1SEL>
__global__ __launch_bounds__(256) void convert_w(const float* __restrict__ W) {
    __shared__ float tb[64 * 65];
    const int K = W1SEL ? CDIM : HDIM;
    const int N = W1SEL ? HDIM : CDIM;
    __nv_bfloat16* Wt = W1SEL ? g_w1t : g_w2t;
    const float shift = W1SEL ? 0.5f : 0.0f;
    const int e = blockIdx.z;
    const int k0 = blockIdx.x * 64, n0 = blockIdx.y * 64;
    const int tid = threadIdx.x;
    const float* Wp = W + (size_t)e * K * N;

    #pragma unroll
    for (int p = 0; p < 4; ++p) {
        const int idx = tid + p * 256;
        const int row = idx >> 4;
        const int c4  = (idx & 15) * 4;
        const float4 v = *reinterpret_cast<const float4*>(
            &Wp[(size_t)(k0 + row) * N + n0 + c4]);
        float* d = &tb[row * 65 + c4];
        d[0] = v.x; d[1] = v.y; d[2] = v.z; d[3] = v.w;
    }
    __syncthreads();

    __nv_bfloat16* Wo = Wt + (size_t)e * N * K;
    #pragma unroll
    for (int p = 0; p < 2; ++p) {
        const int idx = tid + p * 256;
        const int nrow = idx >> 3;
        const int kseg = (idx & 7) * 8;
        __nv_bfloat162 b[4];
        #pragma unroll
        for (int j = 0; j < 4; ++j)
            b[j] = __floats2bfloat162_rn(tb[(kseg + 2*j    ) * 65 + nrow] - shift,
                                         tb[(kseg + 2*j + 1) * 65 + nrow] - shift);
        *reinterpret_cast<uint4*>(&Wo[(size_t)(n0 + nrow) * K + k0 + kseg]) =
            *reinterpret_cast<const uint4*>(b);
    }
}

// ---- grouped GEMM: BM=BN=128, warp tile 64x32, 2 CTAs/SM, 3 stages ------
#define TILE0       2048
#define STAGE_BYTES 32768
#define A_BYTES     16384
#define SMEM_TOTAL  (TILE0 + STAGES * STAGE_BYTES)   // 100352 -> 2 CTAs/SM

template<int KDIM, int NDIM, bool FFN1>
__global__ __launch_bounds__(256, 2) void moe_gemm2(
    const float* __restrict__ bias, float* __restrict__ out)
{
    const int e   = blockIdx.z;
    const int cnt = g_cnt[e];
    const int m0  = blockIdx.y * BM;
    if (m0 >= cnt) return;
    const int n0  = blockIdx.x * BN;

    extern __shared__ __align__(1024) char smem[];
    int*   toks = (int*)(smem);            // 128 ints
    float* cs   = (float*)(smem + 512);    // 128 floats
    float* bs   = (float*)(smem + 1024);   // 128 floats
    const uint32_t tiles = smem_u32(smem + TILE0);

    const int tid = threadIdx.x, lane = tid & 31, wid = tid >> 5;

    if (tid < BM) {
        const int tk = g_tok[e * NTOK + min(m0 + tid, cnt - 1)];
        toks[tid] = tk;
        cs[tid]   = FFN1 ? 0.5f * g_xsum[tk] : g_score[tk];
        bs[tid]   = bias[(size_t)e * NDIM + n0 + tid];
    }
    __syncthreads();

    // ---- staging: thread -> (16B chunk, rows rbase+32i), XOR swizzle ----
    const __nv_bfloat16* __restrict__ A  = FFN1 ? g_xb  : g_h;
    const __nv_bfloat16* __restrict__ Wt = (FFN1 ? g_w1t : g_w2t) + (size_t)e * NDIM * KDIM;
    const int chunk = tid & 7;
    const int rbase = tid >> 3;                      // 0..31
    const uint32_t sw    = (uint32_t)((chunk ^ (rbase & 7)) * 16);
    const uint32_t roff0 = (uint32_t)(rbase * 128) + sw;
    const __nv_bfloat16* aptr[4];
    #pragma unroll
    for (int i = 0; i < 4; ++i)
        aptr[i] = A + (size_t)toks[rbase + i * 32] * KDIM + chunk * 8;
    const __nv_bfloat16* bptr0 = Wt + (size_t)(n0 + rbase) * KDIM + chunk * 8;

    auto load_tile = [&](int t, int s) {
        const uint32_t sa = tiles + s * STAGE_BYTES;
        const uint32_t sb = sa + A_BYTES;
        const int ke = t * BK;
        #pragma unroll
        for (int i = 0; i < 4; ++i)
            cpa16(sa + roff0 + i * 4096, aptr[i] + ke);
        #pragma unroll
        for (int i = 0; i < 4; ++i)
            cpa16(sb + roff0 + i * 4096, bptr0 + (size_t)i * 32 * KDIM + ke);
        cpa_commit();
    };

    // ---- warp tiling: 2 (M) x 4 (N) warps, warp tile 64x32 ----
    const int wm = (wid & 1) * 64;
    const int wn = (wid >> 1) * 32;
    const int lane15 = lane & 15;
    const int laneh  = lane >> 4;

    uint32_t arow128[4], arow7[4], brow128[2], brow7[2];
    #pragma unroll
    for (int i = 0; i < 4; ++i) {
        const int ra = wm + i * 16 + lane15;
        arow128[i] = (uint32_t)(ra * 128); arow7[i] = (uint32_t)(ra & 7);
    }
    #pragma unroll
    for (int i = 0; i < 2; ++i) {
        const int rb = wn + i * 16 + lane15;
        brow128[i] = (uint32_t)(rb * 128); brow7[i] = (uint32_t)(rb & 7);
    }

    float c[4][4][4];
    #pragma unroll
    for (int mi = 0; mi < 4; ++mi)
        #pragma unroll
        for (int ni = 0; ni < 4; ++ni)
            #pragma unroll
            for (int q = 0; q < 4; ++q) c[mi][ni][q] = 0.f;

    const int T = KDIM / BK;
    load_tile(0, 0);
    load_tile(1, 1);

    for (int t = 0; t < T; ++t) {
        const int s = t % STAGES;
        cpa_wait1();
        __syncthreads();
        if (t + 2 < T) load_tile(t + 2, (t + 2) % STAGES);
        else cpa_commit();                 // keep group accounting uniform

        const uint32_t Ab = tiles + s * STAGE_BYTES;
        const uint32_t Bb = Ab + A_BYTES;
        #pragma unroll
        for (int ki = 0; ki < 4; ++ki) {
            const uint32_t ck = (uint32_t)(ki * 2 + laneh);
            uint32_t a[4][4], b[2][4];
            #pragma unroll
            for (int i = 0; i < 4; ++i)
                ldsm_x4(a[i], Ab + arow128[i] + ((ck ^ arow7[i]) << 4));
            #pragma unroll
            for (int i = 0; i < 2; ++i)
                ldsm_x4(b[i], Bb + brow128[i] + ((ck ^ brow7[i]) << 4));
            #pragma unroll
            for (int mi = 0; mi < 4; ++mi)
                #pragma unroll
                for (int n8 = 0; n8 < 4; ++n8) {
                    const int ni = n8 >> 1, o = n8 & 1;
                    mma_bf16(c[mi][n8], a[mi], b[ni][o], b[ni][o + 2]);
                }
        }
    }

    // ---------------- epilogue ----------------
    const int g  = lane >> 2;
    const int t4 = lane & 3;
    #pragma unroll
    for (int mi = 0; mi < 4; ++mi) {
        #pragma unroll
        for (int h = 0; h < 2; ++h) {
            const int r = wm + mi * 16 + g + h * 8;
            if (m0 + r < cnt) {
                const int   tok  = toks[r];
                const float corr = cs[r];
                #pragma unroll
                for (int n8 = 0; n8 < 4; ++n8) {
                    const int col = wn + n8 * 8 + t4 * 2;
                    const float v0 = c[mi][n8][h * 2 + 0] + bs[col];
                    const float v1 = c[mi][n8][h * 2 + 1] + bs[col + 1];
                    if (FFN1) {
                        *reinterpret_cast<__nv_bfloat162*>(
                            &g_h[(size_t)tok * HDIM + n0 + col]) =
                            __floats2bfloat162_rn(gelu_exact(v0 + corr),
                                                  gelu_exact(v1 + corr));
                    } else {
                        float2 o2;
                        o2.x = v0 * corr;
                        o2.y = v1 * corr;
                        *reinterpret_cast<float2*>(
                            &out[(size_t)tok * CDIM + n0 + col]) = o2;
                    }
                }
            }
        }
    }
}

// ---------------- launch: fork/join stream topology (validated R12) ------
extern "C" void kernel_launch(void* const* d_in, const int* in_sizes, int n_in,
                              void* d_out, int out_size) {
    (void)in_sizes; (void)n_in; (void)out_size;
    const float* x  = (const float*)d_in[0];
    const float* Wr = (const float*)d_in[1];
    const float* wg = (const float*)d_in[2];
    const float* W1 = (const float*)d_in[3];
    const float* b1 = (const float*)d_in[4];
    const float* W2 = (const float*)d_in[5];
    const float* b2 = (const float*)d_in[6];
    float* out = (float*)d_out;

    cudaFuncSetAttribute(moe_gemm2<CDIM, HDIM, true>,
                         cudaFuncAttributeMaxDynamicSharedMemorySize, SMEM_TOTAL);
    cudaFuncSetAttribute(moe_gemm2<HDIM, CDIM, false>,
                         cudaFuncAttributeMaxDynamicSharedMemorySize, SMEM_TOTAL);

    cudaStream_t s2;
    cudaStreamCreateWithFlags(&s2, cudaStreamNonBlocking);
    cudaEvent_t evZero, evRoute, evConv2;
    cudaEventCreateWithFlags(&evZero,  cudaEventDisableTiming);
    cudaEventCreateWithFlags(&evRoute, cudaEventDisableTiming);
    cudaEventCreateWithFlags(&evConv2, cudaEventDisableTiming);

    zero_cnt_kernel<<<1, 32>>>();
    cudaEventRecord(evZero, 0);

    cudaStreamWaitEvent(s2, evZero, 0);
    route_kernel<<<NTOK / (4 * 8), 256, 0, s2>>>(x, Wr, wg);
    cudaEventRecord(evRoute, s2);
    convert_w<false><<<dim3(HDIM / 64, CDIM / 64, NEXP), 256, 0, s2>>>(W2);
    cudaEventRecord(evConv2, s2);

    convert_w<true ><<<dim3(CDIM / 64, HDIM / 64, NEXP), 256>>>(W1);
    cudaStreamWaitEvent(0, evRoute, 0);
    moe_gemm2<CDIM, HDIM, true ><<<dim3(HDIM / BN, NTOK / BM, NEXP), 256, SMEM_TOTAL>>>(b1, nullptr);
    cudaStreamWaitEvent(0, evConv2, 0);
    moe_gemm2<HDIM, CDIM, false><<<dim3(CDIM / BN, NTOK / BM, NEXP), 256, SMEM_TOTAL>>>(b2, out);

    cudaEventDestroy(evZero);
    cudaEventDestroy(evRoute);
    cudaEventDestroy(evConv2);
    cudaStreamDestroy(s2);
}